// round 1
// baseline (speedup 1.0000x reference)
#include <cuda_runtime.h>

#define EPS 1e-5f

typedef unsigned long long u64;

union f2u { u64 u; float2 f; };

__device__ __forceinline__ u64 pack2(float lo, float hi) {
    u64 r; asm("mov.b64 %0, {%1,%2};" : "=l"(r) : "f"(lo), "f"(hi)); return r;
}
__device__ __forceinline__ void ffma2(u64 &d, u64 a, u64 b) {
    asm("fma.rn.f32x2 %0, %1, %2, %0;" : "+l"(d) : "l"(a), "l"(b));
}

// Scratch: qkv[n=8][o=256][h=128][w=128] fp32 = 128 MB (static device global; no allocs)
__device__ float g_qkv[33554432];

// ---------------- Kernel 1: QKV GEMM + BN ----------------
// Y[n][o][p] = sum_c W[o][c] * x[n][c][p],  p = h*128 + w, then BN over o.
// Tiles: 64 o x 64 p per block, K chunked by 64. f32x2 accumulation.
__global__ __launch_bounds__(256) void qkv_kernel(
    const float* __restrict__ x, const float* __restrict__ w,
    const float* __restrict__ qg, const float* __restrict__ qb,
    const float* __restrict__ qm, const float* __restrict__ qv) {
    __shared__ float xs[64][64];   // [c][p]
    __shared__ float ws[64][68];   // [c][o], padded
    int tid = threadIdx.x;
    int pt = blockIdx.x, ot = blockIdx.y, n = blockIdx.z;
    const float* xp = x + (size_t)n * (128 * 16384) + pt * 64;
    const float* wp = w + ot * 64 * 128;
    int ty = tid >> 4, tx = tid & 15;
    int ob = ty * 4, pb = tx * 4;

    f2u acc[4][2];
#pragma unroll
    for (int a = 0; a < 4; a++) { acc[a][0].u = 0ull; acc[a][1].u = 0ull; }

    for (int cc = 0; cc < 2; cc++) {
        // load x chunk: 64c x 64p
#pragma unroll
        for (int k = 0; k < 4; k++) {
            int f = tid + k * 256;
            int c = f >> 4, p4 = (f & 15) << 2;
            *(float4*)&xs[c][p4] =
                *(const float4*)(xp + (size_t)(cc * 64 + c) * 16384 + p4);
        }
        // load w chunk transposed: [c][o]
#pragma unroll
        for (int k = 0; k < 16; k++) {
            int f = tid + k * 256;
            int o = f >> 6, c = f & 63;
            ws[c][o] = wp[o * 128 + cc * 64 + c];
        }
        __syncthreads();
#pragma unroll
        for (int c = 0; c < 64; c++) {
            float4 xv = *(float4*)&xs[c][pb];
            float4 wv = *(float4*)&ws[c][ob];
            u64 b0 = pack2(xv.x, xv.y);
            u64 b1 = pack2(xv.z, xv.w);
            u64 a0 = pack2(wv.x, wv.x);
            u64 a1 = pack2(wv.y, wv.y);
            u64 a2 = pack2(wv.z, wv.z);
            u64 a3 = pack2(wv.w, wv.w);
            ffma2(acc[0][0].u, a0, b0); ffma2(acc[0][1].u, a0, b1);
            ffma2(acc[1][0].u, a1, b0); ffma2(acc[1][1].u, a1, b1);
            ffma2(acc[2][0].u, a2, b0); ffma2(acc[2][1].u, a2, b1);
            ffma2(acc[3][0].u, a3, b0); ffma2(acc[3][1].u, a3, b1);
        }
        __syncthreads();
    }
    // BN epilogue + store
#pragma unroll
    for (int oo = 0; oo < 4; oo++) {
        int o = ot * 64 + ob + oo;
        float s = qg[o] * rsqrtf(qv[o] + EPS);
        float t = qb[o] - qm[o] * s;
        float4 r;
        r.x = acc[oo][0].f.x * s + t;
        r.y = acc[oo][0].f.y * s + t;
        r.z = acc[oo][1].f.x * s + t;
        r.w = acc[oo][1].f.y * s + t;
        *(float4*)(g_qkv + (size_t)(n * 256 + o) * 16384 + pt * 64 + pb) = r;
    }
}

// ---------------- Kernel 2: attention per (n, g, 8-wide w tile) ----------------
// smem layout (floats):
//   qkv_t [8w][32ch][128h] : 0      .. 32768
//   ostage[16c][128h][8w]  : 32768  .. 49152
//   redm  [2][128]         : 49152  .. 49408
//   reds  [2][128]         : 49408  .. 49664
//   obuf  [16][128]        : 49664  .. 51712
//   osc[16], osh[16]       : 51712  .. 51744
// total = 51744 * 4 = 206976 bytes
#define SMEM2 206976

__global__ __launch_bounds__(256) void attn_kernel(
    const float* __restrict__ simg, const float* __restrict__ simv,
    const float* __restrict__ og, const float* __restrict__ obt,
    const float* __restrict__ om, const float* __restrict__ ov,
    float* __restrict__ out) {
    extern __shared__ float sm2[];
    float* qkv_t  = sm2;
    float* ostage = sm2 + 32768;
    float* redm   = sm2 + 49152;
    float* reds   = sm2 + 49408;
    float* obuf   = sm2 + 49664;
    float* osc    = sm2 + 51712;
    float* osh    = sm2 + 51728;

    int tid = threadIdx.x;
    int w0 = blockIdx.x * 8;
    int g  = blockIdx.y;
    int n  = blockIdx.z;

    // Load 32ch x 128h x 8w tile (coalesced 32B chunks), transpose into [w][ch][h]
    const float* src = g_qkv + (size_t)(n * 256 + g * 32) * 16384 + w0;
#pragma unroll
    for (int k = 0; k < 32; k++) {
        int f = tid + k * 256;
        int half = f & 1;
        int h = (f >> 1) & 127;
        int ch = f >> 8;
        float4 v4 = *(const float4*)(src + (size_t)ch * 16384 + h * 128 + half * 4);
        int wb = half * 4;
        qkv_t[((wb + 0) * 32 + ch) * 128 + h] = v4.x;
        qkv_t[((wb + 1) * 32 + ch) * 128 + h] = v4.y;
        qkv_t[((wb + 2) * 32 + ch) * 128 + h] = v4.z;
        qkv_t[((wb + 3) * 32 + ch) * 128 + h] = v4.w;
    }
    if (tid < 16) {
        int co = g * 16 + tid;
        float s = og[co] * rsqrtf(ov[co] + EPS);
        osc[tid] = s;
        osh[tid] = obt[co] - om[co] * s;
    }
    // sim BN: shift is constant over j -> cancels in softmax; only scale matters.
    float simscale = simg[g] * rsqrtf(simv[g] + EPS);
    __syncthreads();

    int half = tid >> 7;     // 0/1: which 64-wide j half this thread owns
    int i = tid & 127;       // row
    int j0 = half * 64;

#pragma unroll 1
    for (int ww = 0; ww < 8; ww++) {
        const float* Q = qkv_t + ww * 32 * 128;
        // q row in registers, pre-scaled by sim BN scale, duplicated for f32x2
        u64 qd[8];
#pragma unroll
        for (int c = 0; c < 8; c++) {
            float qvv = Q[c * 128 + i] * simscale;
            qd[c] = pack2(qvv, qvv);
        }
        // S[i][j0..j0+63] in registers (32 f32x2 pairs)
        f2u s2[32];
#pragma unroll
        for (int k = 0; k < 32; k++) s2[k].u = 0ull;
#pragma unroll
        for (int jj = 0; jj < 64; jj += 4) {
#pragma unroll
            for (int c = 0; c < 8; c++) {
                float4 k4 = *(const float4*)(Q + (8 + c) * 128 + j0 + jj);
                ffma2(s2[jj / 2].u,     qd[c], pack2(k4.x, k4.y));
                ffma2(s2[jj / 2 + 1].u, qd[c], pack2(k4.z, k4.w));
            }
        }
        // softmax: row max across halves
        float mx = -1e30f;
#pragma unroll
        for (int k = 0; k < 32; k++)
            mx = fmaxf(mx, fmaxf(s2[k].f.x, s2[k].f.y));
        redm[half * 128 + i] = mx;
        __syncthreads();
        mx = fmaxf(redm[i], redm[128 + i]);
        float sum = 0.f;
#pragma unroll
        for (int k = 0; k < 32; k++) {
            float e0 = __expf(s2[k].f.x - mx);
            float e1 = __expf(s2[k].f.y - mx);
            s2[k].f.x = e0; s2[k].f.y = e1;
            sum += e0 + e1;
        }
        reds[half * 128 + i] = sum;
        __syncthreads();
        float inv = 1.f / (reds[i] + reds[128 + i]);
        // O[c][i] partial over this thread's j half (e pairs already packed in s2)
        f2u oc[16];
#pragma unroll
        for (int c = 0; c < 16; c++) oc[c].u = 0ull;
#pragma unroll
        for (int jj = 0; jj < 64; jj += 4) {
            u64 e0 = s2[jj / 2].u;
            u64 e1 = s2[jj / 2 + 1].u;
#pragma unroll
            for (int c = 0; c < 16; c++) {
                float4 v4 = *(const float4*)(Q + (16 + c) * 128 + j0 + jj);
                ffma2(oc[c].u, e0, pack2(v4.x, v4.y));
                ffma2(oc[c].u, e1, pack2(v4.z, v4.w));
            }
        }
        if (half) {
#pragma unroll
            for (int c = 0; c < 16; c++)
                obuf[c * 128 + i] = oc[c].f.x + oc[c].f.y;
        }
        __syncthreads();
        if (!half) {
#pragma unroll
            for (int c = 0; c < 16; c++) {
                float t = (oc[c].f.x + oc[c].f.y + obuf[c * 128 + i]) * inv;
                ostage[(c * 128 + i) * 8 + ww] = t * osc[c] + osh[c];
            }
        }
        __syncthreads();
    }
    // cooperative write-out: 8 contiguous w per (co, h) row
    float* dst = out + (size_t)(n * 128 + g * 16) * 16384 + w0;
#pragma unroll
    for (int k = 0; k < 8; k++) {
        int f = tid + k * 256;
        int c = f >> 7, h = f & 127;
        float4 a = *(float4*)&ostage[(c * 128 + h) * 8];
        float4 b = *(float4*)&ostage[(c * 128 + h) * 8 + 4];
        float4* d = (float4*)(dst + (size_t)c * 16384 + h * 128);
        d[0] = a; d[1] = b;
    }
}

extern "C" void kernel_launch(void* const* d_in, const int* in_sizes, int n_in,
                              void* d_out, int out_size) {
    const float* x    = (const float*)d_in[0];
    const float* wq   = (const float*)d_in[1];
    const float* qg   = (const float*)d_in[2];
    const float* qb   = (const float*)d_in[3];
    const float* qm   = (const float*)d_in[4];
    const float* qv   = (const float*)d_in[5];
    const float* simg = (const float*)d_in[6];
    // d_in[7] sim_beta, d_in[8] sim_mean: shift cancels in softmax (constant over j)
    const float* simv = (const float*)d_in[9];
    const float* og   = (const float*)d_in[10];
    const float* obt  = (const float*)d_in[11];
    const float* om   = (const float*)d_in[12];
    const float* ov   = (const float*)d_in[13];
    float* out = (float*)d_out;

    cudaFuncSetAttribute(attn_kernel,
                         cudaFuncAttributeMaxDynamicSharedMemorySize, SMEM2);

    // Kernel 1: QKV GEMM + BN -> scratch
    qkv_kernel<<<dim3(256, 4, 8), 256>>>(x, wq, qg, qb, qm, qv);
    // Kernel 2: fused attention + out BN + transposed store
    attn_kernel<<<dim3(16, 8, 8), 256, SMEM2>>>(simg, simv, og, obt, om, ov, out);
}

// round 2
// speedup vs baseline: 1.1069x; 1.1069x over previous
#include <cuda_runtime.h>

#define EPS 1e-5f

typedef unsigned long long u64;

union f2u { u64 u; float2 f; };

__device__ __forceinline__ u64 pack2(float lo, float hi) {
    u64 r; asm("mov.b64 %0, {%1,%2};" : "=l"(r) : "f"(lo), "f"(hi)); return r;
}
__device__ __forceinline__ void ffma2(u64 &d, u64 a, u64 b) {
    asm("fma.rn.f32x2 %0, %1, %2, %0;" : "+l"(d) : "l"(a), "l"(b));
}

// Scratch: qkv[n=8][o=256][h=128][w=128] fp32 = 128 MB (static device global)
__device__ float g_qkv[33554432];

// ---------------- Kernel 1: QKV GEMM + BN ----------------
// Y[n][o][p] = sum_c W[o][c] * x[n][c][p]. Block tile: 128o x 64p, K chunk 64.
// Thread tile: 8o x 4p (f32x2).
__global__ __launch_bounds__(256) void qkv_kernel(
    const float* __restrict__ x, const float* __restrict__ w,
    const float* __restrict__ qg, const float* __restrict__ qb,
    const float* __restrict__ qm, const float* __restrict__ qv) {
    __shared__ float xs[64][64];    // [c][p]
    __shared__ float ws[64][132];   // [c][o], padded (132 % 4 == 0)
    int tid = threadIdx.x;
    int pt = blockIdx.x, ot = blockIdx.y, n = blockIdx.z;
    const float* xp = x + (size_t)n * (128 * 16384) + pt * 64;
    const float* wp = w + ot * 128 * 128;
    int ob = (tid >> 4) * 8;      // 16 groups x 8 o = 128 o
    int pb = (tid & 15) * 4;      // 16 groups x 4 p = 64 p

    f2u acc[8][2];
#pragma unroll
    for (int a = 0; a < 8; a++) { acc[a][0].u = 0ull; acc[a][1].u = 0ull; }

    for (int cc = 0; cc < 2; cc++) {
        // x chunk: 64c x 64p (coalesced float4)
#pragma unroll
        for (int k = 0; k < 4; k++) {
            int f = tid + k * 256;
            int c = f >> 4, p4 = (f & 15) << 2;
            *(float4*)&xs[c][p4] =
                *(const float4*)(xp + (size_t)(cc * 64 + c) * 16384 + p4);
        }
        // w chunk transposed: [c][o], 64 x 128
#pragma unroll
        for (int k = 0; k < 32; k++) {
            int f = tid + k * 256;
            int o = f >> 6, c = f & 63;
            ws[c][o] = wp[o * 128 + cc * 64 + c];
        }
        __syncthreads();
#pragma unroll 8
        for (int c = 0; c < 64; c++) {
            float4 xv = *(float4*)&xs[c][pb];
            u64 b0 = pack2(xv.x, xv.y);
            u64 b1 = pack2(xv.z, xv.w);
            float4 w0 = *(float4*)&ws[c][ob];
            float4 w1 = *(float4*)&ws[c][ob + 4];
            u64 a0 = pack2(w0.x, w0.x), a1 = pack2(w0.y, w0.y);
            u64 a2 = pack2(w0.z, w0.z), a3 = pack2(w0.w, w0.w);
            u64 a4 = pack2(w1.x, w1.x), a5 = pack2(w1.y, w1.y);
            u64 a6 = pack2(w1.z, w1.z), a7 = pack2(w1.w, w1.w);
            ffma2(acc[0][0].u, a0, b0); ffma2(acc[0][1].u, a0, b1);
            ffma2(acc[1][0].u, a1, b0); ffma2(acc[1][1].u, a1, b1);
            ffma2(acc[2][0].u, a2, b0); ffma2(acc[2][1].u, a2, b1);
            ffma2(acc[3][0].u, a3, b0); ffma2(acc[3][1].u, a3, b1);
            ffma2(acc[4][0].u, a4, b0); ffma2(acc[4][1].u, a4, b1);
            ffma2(acc[5][0].u, a5, b0); ffma2(acc[5][1].u, a5, b1);
            ffma2(acc[6][0].u, a6, b0); ffma2(acc[6][1].u, a6, b1);
            ffma2(acc[7][0].u, a7, b0); ffma2(acc[7][1].u, a7, b1);
        }
        __syncthreads();
    }
    // BN epilogue + store
#pragma unroll
    for (int oo = 0; oo < 8; oo++) {
        int o = ot * 128 + ob + oo;
        float s = qg[o] * rsqrtf(qv[o] + EPS);
        float t = qb[o] - qm[o] * s;
        float4 r;
        r.x = acc[oo][0].f.x * s + t;
        r.y = acc[oo][0].f.y * s + t;
        r.z = acc[oo][1].f.x * s + t;
        r.w = acc[oo][1].f.y * s + t;
        *(float4*)(g_qkv + (size_t)(n * 256 + o) * 16384 + pt * 64 + pb) = r;
    }
}

// ---------------- Kernel 2: attention per (n, g, 4-wide w tile) ----------------
// 512 threads: thread = (q = j-quarter of 32, i = row). 16 warps/SM.
// smem layout (floats):
//   qkv_t [4w][32ch][128h] : 0     .. 16384
//   ostage[16c][128h][4w]  : 16384 .. 24576
//   obuf  [3][16c][128h]   : 24576 .. 30720
//   redm  [4][128]         : 30720 .. 31232
//   reds  [4][128]         : 31232 .. 31744
//   osc[16], osh[16]       : 31744 .. 31776
#define SMEM2 (31776 * 4)

__global__ __launch_bounds__(512) void attn_kernel(
    const float* __restrict__ simg, const float* __restrict__ simv,
    const float* __restrict__ og, const float* __restrict__ obt,
    const float* __restrict__ om, const float* __restrict__ ov,
    float* __restrict__ out) {
    extern __shared__ float sm2[];
    float* qkv_t  = sm2;
    float* ostage = sm2 + 16384;
    float* obuf   = sm2 + 24576;
    float* redm   = sm2 + 30720;
    float* reds   = sm2 + 31232;
    float* osc    = sm2 + 31744;
    float* osh    = sm2 + 31760;

    int tid = threadIdx.x;
    int w0 = blockIdx.x * 4;
    int g  = blockIdx.y;
    int n  = blockIdx.z;

    // Load 32ch x 128h x 4w tile; each float4 covers the 4 w's -> scatter [w][ch][h]
    const float* src = g_qkv + (size_t)(n * 256 + g * 32) * 16384 + w0;
#pragma unroll
    for (int k = 0; k < 8; k++) {
        int f = tid + k * 512;
        int h = f & 127;
        int ch = f >> 7;
        float4 v4 = *(const float4*)(src + (size_t)ch * 16384 + h * 128);
        qkv_t[(0 * 32 + ch) * 128 + h] = v4.x;
        qkv_t[(1 * 32 + ch) * 128 + h] = v4.y;
        qkv_t[(2 * 32 + ch) * 128 + h] = v4.z;
        qkv_t[(3 * 32 + ch) * 128 + h] = v4.w;
    }
    if (tid < 16) {
        int co = g * 16 + tid;
        float s = og[co] * rsqrtf(ov[co] + EPS);
        osc[tid] = s;
        osh[tid] = obt[co] - om[co] * s;
    }
    // sim BN shift cancels in softmax; only (positive) scale matters.
    float simscale = simg[g] * rsqrtf(simv[g] + EPS);
    __syncthreads();

    int q = tid >> 7;        // j quarter (0..3)
    int i = tid & 127;       // row
    int j0 = q * 32;

#pragma unroll 1
    for (int ww = 0; ww < 4; ww++) {
        const float* Q = qkv_t + ww * 32 * 128;
        // q row, pre-scaled, duplicated for f32x2
        u64 qd[8];
#pragma unroll
        for (int c = 0; c < 8; c++) {
            float qvv = Q[c * 128 + i] * simscale;
            qd[c] = pack2(qvv, qvv);
        }
        // S[i][j0..j0+31] (16 f32x2)
        f2u s2[16];
#pragma unroll
        for (int k = 0; k < 16; k++) s2[k].u = 0ull;
#pragma unroll
        for (int jj = 0; jj < 32; jj += 4) {
#pragma unroll
            for (int c = 0; c < 8; c++) {
                float4 k4 = *(const float4*)(Q + (8 + c) * 128 + j0 + jj);
                ffma2(s2[jj / 2].u,     qd[c], pack2(k4.x, k4.y));
                ffma2(s2[jj / 2 + 1].u, qd[c], pack2(k4.z, k4.w));
            }
        }
        // softmax across the 4 quarters
        float mx = -1e30f;
#pragma unroll
        for (int k = 0; k < 16; k++)
            mx = fmaxf(mx, fmaxf(s2[k].f.x, s2[k].f.y));
        redm[q * 128 + i] = mx;
        __syncthreads();
        mx = fmaxf(fmaxf(redm[i], redm[128 + i]),
                   fmaxf(redm[256 + i], redm[384 + i]));
        float sum = 0.f;
#pragma unroll
        for (int k = 0; k < 16; k++) {
            float e0 = __expf(s2[k].f.x - mx);
            float e1 = __expf(s2[k].f.y - mx);
            s2[k].f.x = e0; s2[k].f.y = e1;
            sum += e0 + e1;
        }
        reds[q * 128 + i] = sum;
        __syncthreads();
        float inv = 1.f / (reds[i] + reds[128 + i] + reds[256 + i] + reds[384 + i]);
        // O[c][i] partial over this thread's j quarter
        f2u oc[16];
#pragma unroll
        for (int c = 0; c < 16; c++) oc[c].u = 0ull;
#pragma unroll
        for (int jj = 0; jj < 32; jj += 4) {
            u64 e0 = s2[jj / 2].u;
            u64 e1 = s2[jj / 2 + 1].u;
#pragma unroll
            for (int c = 0; c < 16; c++) {
                float4 v4 = *(const float4*)(Q + (16 + c) * 128 + j0 + jj);
                ffma2(oc[c].u, e0, pack2(v4.x, v4.y));
                ffma2(oc[c].u, e1, pack2(v4.z, v4.w));
            }
        }
        if (q) {
#pragma unroll
            for (int c = 0; c < 16; c++)
                obuf[((q - 1) * 16 + c) * 128 + i] = oc[c].f.x + oc[c].f.y;
        }
        __syncthreads();
        if (!q) {
#pragma unroll
            for (int c = 0; c < 16; c++) {
                float t = (oc[c].f.x + oc[c].f.y
                           + obuf[c * 128 + i]
                           + obuf[(16 + c) * 128 + i]
                           + obuf[(32 + c) * 128 + i]) * inv;
                ostage[(c * 128 + i) * 4 + ww] = t * osc[c] + osh[c];
            }
        }
        __syncthreads();
    }
    // cooperative write-out: 4 contiguous w per (c, h) row
    float* dst = out + (size_t)(n * 128 + g * 16) * 16384 + w0;
#pragma unroll
    for (int k = 0; k < 4; k++) {
        int f = tid + k * 512;
        int c = f >> 7, h = f & 127;
        float4 a = *(float4*)&ostage[(c * 128 + h) * 4];
        *(float4*)(dst + (size_t)c * 16384 + h * 128) = a;
    }
}

extern "C" void kernel_launch(void* const* d_in, const int* in_sizes, int n_in,
                              void* d_out, int out_size) {
    const float* x    = (const float*)d_in[0];
    const float* wq   = (const float*)d_in[1];
    const float* qg   = (const float*)d_in[2];
    const float* qb   = (const float*)d_in[3];
    const float* qm   = (const float*)d_in[4];
    const float* qv   = (const float*)d_in[5];
    const float* simg = (const float*)d_in[6];
    // d_in[7] sim_beta, d_in[8] sim_mean: shift cancels in softmax
    const float* simv = (const float*)d_in[9];
    const float* og   = (const float*)d_in[10];
    const float* obt  = (const float*)d_in[11];
    const float* om   = (const float*)d_in[12];
    const float* ov   = (const float*)d_in[13];
    float* out = (float*)d_out;

    cudaFuncSetAttribute(attn_kernel,
                         cudaFuncAttributeMaxDynamicSharedMemorySize, SMEM2);

    qkv_kernel<<<dim3(256, 2, 8), 256>>>(x, wq, qg, qb, qm, qv);
    attn_kernel<<<dim3(32, 8, 8), 512, SMEM2>>>(simg, simv, og, obt, om, ov, out);
}